// round 2
// baseline (speedup 1.0000x reference)
#include <cuda_runtime.h>
#include <math.h>

#define Bb 256
#define Ll 256
#define Dd 768
#define Hh 1024
#define Tt 32
#define KV (3*Dd)   // 2304
#define Gg (4*Hh)   // 4096
#define NL (3*Ll)   // 768

// ---------- scratch (device globals: no allocations allowed) ----------
__device__ float g_h[Bb*Hh];
__device__ float g_c[Bb*Hh];
__device__ float g_att[Bb*NL];     // logits, then attention weights in-place
__device__ float g_v[Bb*KV];       // concat(v1,v2,v3)
__device__ float g_gates[Bb*Gg];

// ---------- init ----------
__global__ void init_kernel(const float* __restrict__ h0, const float* __restrict__ c0) {
    int i = blockIdx.x * blockDim.x + threadIdx.x;
    if (i < Bb*Hh) { g_h[i] = h0[i]; g_c[i] = c0[i]; }
}

// ---------- logits: g_att[B, 3L] = h @ Wk^T + bk  (Wk selected per 64-col tile) ----------
// tile 64x64, K-tile 32, 256 threads, 4x4 per thread
__global__ void logits_kernel(const float* __restrict__ W1, const float* __restrict__ b1,
                              const float* __restrict__ W2, const float* __restrict__ b2,
                              const float* __restrict__ W3, const float* __restrict__ b3) {
    __shared__ float As[32][68];  // As[k][rowInTile]  (h rows)
    __shared__ float Ws[32][68];  // Ws[k][colInTile]  (W rows)
    const int tx = threadIdx.x, ty = threadIdx.y;
    const int t  = ty * 16 + tx;
    const int row0 = blockIdx.y * 64;        // batch
    const int col0 = blockIdx.x * 64;        // logit column (0..767)
    const int which = blockIdx.x >> 2;       // 0,1,2 -> W1,W2,W3 (4 tiles of 64 per head)
    const float* W = (which == 0) ? W1 : (which == 1) ? W2 : W3;
    const float* bias = (which == 0) ? b1 : (which == 1) ? b2 : b3;
    const int jbase = col0 - which * Ll;

    float acc[4][4] = {};
    for (int k0 = 0; k0 < Hh; k0 += 32) {
        #pragma unroll
        for (int m = 0; m < 8; m++) {
            int idx = t + m * 256;           // 0..2047
            int kk = idx & 31, ii = idx >> 5;
            As[kk][ii] = g_h[(row0 + ii) * Hh + k0 + kk];
            Ws[kk][ii] = W[(jbase + ii) * Hh + k0 + kk];
        }
        __syncthreads();
        #pragma unroll
        for (int kk = 0; kk < 32; kk++) {
            float4 av = *(const float4*)&As[kk][ty * 4];
            float4 wv = *(const float4*)&Ws[kk][tx * 4];
            float a[4] = {av.x, av.y, av.z, av.w};
            float w[4] = {wv.x, wv.y, wv.z, wv.w};
            #pragma unroll
            for (int r = 0; r < 4; r++)
                #pragma unroll
                for (int c = 0; c < 4; c++)
                    acc[r][c] += a[r] * w[c];
        }
        __syncthreads();
    }
    #pragma unroll
    for (int r = 0; r < 4; r++) {
        int row = row0 + ty * 4 + r;
        #pragma unroll
        for (int c = 0; c < 4; c++) {
            int jl = tx * 4 + c;
            g_att[row * NL + col0 + jl] = acc[r][c] + bias[jbase + jl];
        }
    }
}

// ---------- softmax over L per (batch, head) ----------
__global__ void softmax_kernel() {
    int b = blockIdx.x, k = blockIdx.y;
    float* row = &g_att[b * NL + k * Ll];
    int t = threadIdx.x;  // 256
    __shared__ float red[256];
    float v = row[t];
    red[t] = v; __syncthreads();
    for (int s = 128; s > 0; s >>= 1) { if (t < s) red[t] = fmaxf(red[t], red[t + s]); __syncthreads(); }
    float m = red[0]; __syncthreads();
    float e = expf(v - m);
    red[t] = e; __syncthreads();
    for (int s = 128; s > 0; s >>= 1) { if (t < s) red[t] += red[t + s]; __syncthreads(); }
    row[t] = e / red[0];
}

// ---------- v_k = sum_l a_k[b,l] * x[b,l,:]  (all 3 heads in ONE pass over x) ----------
// block = one batch, 192 threads (float4 over D=768)
__global__ void attnv_kernel(const float* __restrict__ x) {
    int b = blockIdx.x;
    int t = threadIdx.x;  // 0..191
    __shared__ float a1[Ll], a2[Ll], a3[Ll];
    const float* att = &g_att[b * NL];
    for (int i = t; i < Ll; i += 192) { a1[i] = att[i]; a2[i] = att[Ll + i]; a3[i] = att[2 * Ll + i]; }
    __syncthreads();
    const float4* xb = (const float4*)(x + (size_t)b * Ll * Dd);
    float4 s1 = {0,0,0,0}, s2 = {0,0,0,0}, s3 = {0,0,0,0};
    #pragma unroll 8
    for (int l = 0; l < Ll; l++) {
        float4 xv = xb[l * (Dd/4) + t];
        float w1 = a1[l], w2 = a2[l], w3 = a3[l];
        s1.x += w1*xv.x; s1.y += w1*xv.y; s1.z += w1*xv.z; s1.w += w1*xv.w;
        s2.x += w2*xv.x; s2.y += w2*xv.y; s2.z += w2*xv.z; s2.w += w2*xv.w;
        s3.x += w3*xv.x; s3.y += w3*xv.y; s3.z += w3*xv.z; s3.w += w3*xv.w;
    }
    float4* vout = (float4*)(g_v + (size_t)b * KV);
    vout[t] = s1;
    vout[Dd/4 + t] = s2;
    vout[2*(Dd/4) + t] = s3;
}

// ---------- gates = v @ W_ih^T + h @ W_hh^T + b_ih + b_hh ----------
// tile 64x64, K-tile 32, two K loops (K=2304 then K=1024)
__global__ void gates_kernel(const float* __restrict__ W_ih, const float* __restrict__ W_hh,
                             const float* __restrict__ b_ih, const float* __restrict__ b_hh) {
    __shared__ float As[32][68];
    __shared__ float Ws[32][68];
    const int tx = threadIdx.x, ty = threadIdx.y;
    const int t  = ty * 16 + tx;
    const int row0 = blockIdx.y * 64;        // batch
    const int col0 = blockIdx.x * 64;        // gate column (0..4095)
    float acc[4][4] = {};

    // pass 1: A = g_v [B, 2304], W = W_ih [4096, 2304]
    for (int k0 = 0; k0 < KV; k0 += 32) {
        #pragma unroll
        for (int m = 0; m < 8; m++) {
            int idx = t + m * 256;
            int kk = idx & 31, ii = idx >> 5;
            As[kk][ii] = g_v[(row0 + ii) * KV + k0 + kk];
            Ws[kk][ii] = W_ih[(size_t)(col0 + ii) * KV + k0 + kk];
        }
        __syncthreads();
        #pragma unroll
        for (int kk = 0; kk < 32; kk++) {
            float4 av = *(const float4*)&As[kk][ty * 4];
            float4 wv = *(const float4*)&Ws[kk][tx * 4];
            float a[4] = {av.x, av.y, av.z, av.w};
            float w[4] = {wv.x, wv.y, wv.z, wv.w};
            #pragma unroll
            for (int r = 0; r < 4; r++)
                #pragma unroll
                for (int c = 0; c < 4; c++)
                    acc[r][c] += a[r] * w[c];
        }
        __syncthreads();
    }
    // pass 2: A = g_h [B, 1024], W = W_hh [4096, 1024]
    for (int k0 = 0; k0 < Hh; k0 += 32) {
        #pragma unroll
        for (int m = 0; m < 8; m++) {
            int idx = t + m * 256;
            int kk = idx & 31, ii = idx >> 5;
            As[kk][ii] = g_h[(row0 + ii) * Hh + k0 + kk];
            Ws[kk][ii] = W_hh[(size_t)(col0 + ii) * Hh + k0 + kk];
        }
        __syncthreads();
        #pragma unroll
        for (int kk = 0; kk < 32; kk++) {
            float4 av = *(const float4*)&As[kk][ty * 4];
            float4 wv = *(const float4*)&Ws[kk][tx * 4];
            float a[4] = {av.x, av.y, av.z, av.w};
            float w[4] = {wv.x, wv.y, wv.z, wv.w};
            #pragma unroll
            for (int r = 0; r < 4; r++)
                #pragma unroll
                for (int c = 0; c < 4; c++)
                    acc[r][c] += a[r] * w[c];
        }
        __syncthreads();
    }

    #pragma unroll
    for (int r = 0; r < 4; r++) {
        int row = row0 + ty * 4 + r;
        #pragma unroll
        for (int c = 0; c < 4; c++) {
            int col = col0 + tx * 4 + c;
            g_gates[(size_t)row * Gg + col] = acc[r][c] + b_ih[col] + b_hh[col];
        }
    }
}

// ---------- LSTM pointwise + output write ----------
__device__ __forceinline__ float sigmoidf(float x) { return 1.0f / (1.0f + expf(-x)); }

__global__ void lstm_kernel(float* __restrict__ out, int t_step) {
    int idx = blockIdx.x * blockDim.x + threadIdx.x;  // B*H
    int b = idx >> 10, j = idx & 1023;
    const float* gr = &g_gates[(size_t)b * Gg];
    float ig = gr[j], fg = gr[Hh + j], gg = gr[2*Hh + j], og = gr[3*Hh + j];
    float c = g_c[idx];
    float cn = sigmoidf(fg) * c + sigmoidf(ig) * tanhf(gg);
    float hn = sigmoidf(og) * tanhf(cn);
    g_c[idx] = cn;
    g_h[idx] = hn;
    out[((size_t)b * Tt + t_step) * Hh + j] = hn;
}

// ---------- driver ----------
extern "C" void kernel_launch(void* const* d_in, const int* in_sizes, int n_in,
                              void* d_out, int out_size) {
    (void)in_sizes; (void)n_in; (void)out_size;
    const float* x    = (const float*)d_in[0];
    const float* h0   = (const float*)d_in[1];
    const float* c0   = (const float*)d_in[2];
    const float* W1   = (const float*)d_in[3];
    const float* b1   = (const float*)d_in[4];
    const float* W2   = (const float*)d_in[5];
    const float* b2   = (const float*)d_in[6];
    const float* W3   = (const float*)d_in[7];
    const float* b3   = (const float*)d_in[8];
    const float* W_ih = (const float*)d_in[9];
    const float* W_hh = (const float*)d_in[10];
    const float* b_ih = (const float*)d_in[11];
    const float* b_hh = (const float*)d_in[12];
    float* out = (float*)d_out;

    init_kernel<<<(Bb*Hh + 255)/256, 256>>>(h0, c0);

    dim3 blk(16, 16);
    for (int t = 0; t < Tt; t++) {
        logits_kernel<<<dim3(NL/64, Bb/64), blk>>>(W1, b1, W2, b2, W3, b3);
        softmax_kernel<<<dim3(Bb, 3), 256>>>();
        attnv_kernel<<<Bb, 192>>>(x);
        gates_kernel<<<dim3(Gg/64, Bb/64), blk>>>(W_ih, W_hh, b_ih, b_hh);
        lstm_kernel<<<(Bb*Hh + 255)/256, 256>>>(out, t);
    }
}

// round 4
// speedup vs baseline: 2.3223x; 2.3223x over previous
#include <cuda_runtime.h>
#include <cuda_bf16.h>
#include <mma.h>
#include <cstdint>
#include <math.h>

using namespace nvcuda;

#define Bb 256
#define Ll 256
#define Dd 768
#define Hh 1024
#define Tt 32
#define KV (3*Dd)   // 2304
#define Gg (4*Hh)   // 4096
#define NL (3*Ll)   // 768
#define KCH 64      // K elems per smem chunk
#define LDS 72      // padded smem stride (elems), 144 B

// ======================= device scratch (no allocs allowed) =======================
__device__ float g_c[Bb*Hh];
__device__ float g_att[Bb*NL];
__device__ float g_gates[Bb*Gg];
__device__ float g_biasG[Gg];
__device__ float g_biasA[NL];
__device__ __align__(16) __nv_bfloat16 g_hh_[Bb*Hh], g_hl_[Bb*Hh];
__device__ __align__(16) __nv_bfloat16 g_vh_[Bb*KV], g_vl_[Bb*KV];
__device__ __align__(16) __nv_bfloat16 g_Wah[NL*Hh],  g_Wal[NL*Hh];
__device__ __align__(16) __nv_bfloat16 g_Wihh[Gg*KV], g_Wihl[Gg*KV];
__device__ __align__(16) __nv_bfloat16 g_Whhh[Gg*Hh], g_Whhl[Gg*Hh];

__device__ __forceinline__ void split2(float a, __nv_bfloat16* hi, __nv_bfloat16* lo) {
    __nv_bfloat16 h = __float2bfloat16_rn(a);
    *hi = h;
    *lo = __float2bfloat16_rn(a - __bfloat162float(h));
}

__device__ __forceinline__ uint32_t smem_u32(const void* p) {
    uint32_t a;
    asm("{ .reg .u64 t; cvta.to.shared.u64 t, %1; cvt.u32.u64 %0, t; }" : "=r"(a) : "l"(p));
    return a;
}
__device__ __forceinline__ void cp16(uint32_t s, const void* g) {
    asm volatile("cp.async.cg.shared.global [%0], [%1], 16;" :: "r"(s), "l"(g));
}
#define CP_COMMIT() asm volatile("cp.async.commit_group;" ::: "memory")
#define CP_WAIT(n)  asm volatile("cp.async.wait_group %0;" :: "n"(n) : "memory")

// ======================= prep kernels =======================
__global__ void split_kernel(const float* __restrict__ src, __nv_bfloat16* __restrict__ hi,
                             __nv_bfloat16* __restrict__ lo, int n) {
    for (int i = blockIdx.x * blockDim.x + threadIdx.x; i < n; i += gridDim.x * blockDim.x)
        split2(src[i], &hi[i], &lo[i]);
}

__global__ void bias_prep_kernel(const float* __restrict__ b_ih, const float* __restrict__ b_hh,
                                 const float* __restrict__ b1, const float* __restrict__ b2,
                                 const float* __restrict__ b3) {
    int j = blockIdx.x * blockDim.x + threadIdx.x;
    if (j < Gg) g_biasG[j] = b_ih[j] + b_hh[j];
    if (j < NL) g_biasA[j] = (j < Ll) ? b1[j] : (j < 2*Ll) ? b2[j - Ll] : b3[j - 2*Ll];
}

__global__ void init_kernel(const float* __restrict__ h0, const float* __restrict__ c0) {
    int i = blockIdx.x * blockDim.x + threadIdx.x;
    if (i < Bb*Hh) { split2(h0[i], &g_hh_[i], &g_hl_[i]); g_c[i] = c0[i]; }
}

// ======================= split-bf16 WMMA GEMM =======================
// C[256, Ntot] = (Ah+Al)[256, Ktot] @ (Wh+Wl)[Ntot, Ktot]^T  (no bias; consumers add it)
// MODE 0: logits (A=h, K=1024, W=Wa, C=g_att, BM=64)
// MODE 1: gates  (A=[v|h], K=2304+1024, W=[Wih|Whh], C=g_gates, BM=128)
template <int MODE>
__global__ void __launch_bounds__(256, 1) gemm_split_kernel() {
    constexpr int BM = MODE ? 128 : 64;
    constexpr int BN = 64;
    constexpr int FM = MODE ? 2 : 1;        // 16x16 frags per warp (m)
    constexpr int FN = 2;                    // frags per warp (n)
    constexpr int K1 = MODE ? KV : Hh;
    constexpr int K2 = MODE ? Hh : 0;
    constexpr int NCH = (K1 + K2) / KCH;
    constexpr int Ntot = MODE ? Gg : NL;
    constexpr int SS = (2*BM + 2*BN) * LDS * 2;     // bytes per stage
    constexpr int AOFF = BM * LDS * 2;               // Al offset within stage
    constexpr int BOFF = 2 * BM * LDS * 2;           // Bh offset
    constexpr int BLOFF = BOFF + BN * LDS * 2;       // Bl offset

    extern __shared__ __align__(16) char smem[];
    const uint32_t sb = smem_u32(smem);

    const int tid = threadIdx.x;
    const int wid = tid >> 5;
    const int wm = wid >> 1;                 // 0..3
    const int wn = wid & 1;                  // 0..1
    const int col0 = blockIdx.x * BN;
    const int row0 = blockIdx.y * BM;

    const __nv_bfloat16* A1h = MODE ? g_vh_ : g_hh_;
    const __nv_bfloat16* A1l = MODE ? g_vl_ : g_hl_;
    const __nv_bfloat16* W1h = MODE ? g_Wihh : g_Wah;
    const __nv_bfloat16* W1l = MODE ? g_Wihl : g_Wal;
    float* C = MODE ? g_gates : g_att;

    wmma::fragment<wmma::accumulator, 16, 16, 16, float> acc[FM][FN];
    #pragma unroll
    for (int i = 0; i < FM; i++)
        #pragma unroll
        for (int j = 0; j < FN; j++)
            wmma::fill_fragment(acc[i][j], 0.0f);

    // ---- async loader for chunk kc into stage s ----
    auto load_chunk = [&](int kc, int s) {
        const __nv_bfloat16 *Ah, *Al, *Wh, *Wl;
        int lda, ka;
        if (MODE == 0 || kc < K1 / KCH) {
            Ah = A1h; Al = A1l; Wh = W1h; Wl = W1l; lda = K1; ka = kc * KCH;
        } else {
            Ah = g_hh_; Al = g_hl_; Wh = g_Whhh; Wl = g_Whhl; lda = K2; ka = (kc - K1/KCH) * KCH;
        }
        const uint32_t st = sb + s * SS;
        #pragma unroll
        for (int it = 0; it < BM*8/256; it++) {
            int idx = tid + it * 256;
            int r = idx >> 3, q = idx & 7;
            size_t src = (size_t)(row0 + r) * lda + ka + q * 8;
            uint32_t off = r * (LDS*2) + q * 16;
            cp16(st + off, Ah + src);
            cp16(st + AOFF + off, Al + src);
        }
        #pragma unroll
        for (int it = 0; it < BN*8/256; it++) {
            int idx = tid + it * 256;
            int r = idx >> 3, q = idx & 7;
            size_t src = (size_t)(col0 + r) * lda + ka + q * 8;
            uint32_t off = r * (LDS*2) + q * 16;
            cp16(st + BOFF + off, Wh + src);
            cp16(st + BLOFF + off, Wl + src);
        }
    };

    load_chunk(0, 0);
    CP_COMMIT();

    for (int kc = 0; kc < NCH; kc++) {
        if (kc + 1 < NCH) { load_chunk(kc + 1, (kc + 1) & 1); CP_COMMIT(); CP_WAIT(1); }
        else              { CP_WAIT(0); }
        __syncthreads();

        const char* st = smem + (kc & 1) * SS;
        const __nv_bfloat16* pAh = (const __nv_bfloat16*)st;
        const __nv_bfloat16* pAl = (const __nv_bfloat16*)(st + AOFF);
        const __nv_bfloat16* pBh = (const __nv_bfloat16*)(st + BOFF);
        const __nv_bfloat16* pBl = (const __nv_bfloat16*)(st + BLOFF);

        #pragma unroll
        for (int k16 = 0; k16 < KCH/16; k16++) {
            const int kk = k16 * 16;
            wmma::fragment<wmma::matrix_a, 16, 16, 16, __nv_bfloat16, wmma::row_major> ah[FM], al[FM];
            wmma::fragment<wmma::matrix_b, 16, 16, 16, __nv_bfloat16, wmma::col_major> bh[FN], bl[FN];
            #pragma unroll
            for (int i = 0; i < FM; i++) {
                int rr = wm * (FM*16) + i * 16;
                wmma::load_matrix_sync(ah[i], pAh + rr * LDS + kk, LDS);
                wmma::load_matrix_sync(al[i], pAl + rr * LDS + kk, LDS);
            }
            #pragma unroll
            for (int j = 0; j < FN; j++) {
                int cc = wn * (FN*16) + j * 16;
                wmma::load_matrix_sync(bh[j], pBh + cc * LDS + kk, LDS);
                wmma::load_matrix_sync(bl[j], pBl + cc * LDS + kk, LDS);
            }
            #pragma unroll
            for (int i = 0; i < FM; i++)
                #pragma unroll
                for (int j = 0; j < FN; j++) {
                    wmma::mma_sync(acc[i][j], ah[i], bh[j], acc[i][j]);
                    wmma::mma_sync(acc[i][j], ah[i], bl[j], acc[i][j]);
                    wmma::mma_sync(acc[i][j], al[i], bh[j], acc[i][j]);
                }
        }
        __syncthreads();
    }

    #pragma unroll
    for (int i = 0; i < FM; i++)
        #pragma unroll
        for (int j = 0; j < FN; j++) {
            int row = row0 + wm * (FM*16) + i * 16;
            int col = col0 + wn * (FN*16) + j * 16;
            wmma::store_matrix_sync(&C[(size_t)row * Ntot + col], acc[i][j], Ntot, wmma::mem_row_major);
        }
}

// ======================= softmax (adds bias) =======================
__global__ void softmax_kernel() {
    int b = blockIdx.x, k = blockIdx.y;
    float* row = &g_att[b * NL + k * Ll];
    int t = threadIdx.x;
    __shared__ float red[256];
    float v = row[t] + g_biasA[k * Ll + t];
    red[t] = v; __syncthreads();
    for (int s = 128; s > 0; s >>= 1) { if (t < s) red[t] = fmaxf(red[t], red[t + s]); __syncthreads(); }
    float m = red[0]; __syncthreads();
    float e = expf(v - m);
    red[t] = e; __syncthreads();
    for (int s = 128; s > 0; s >>= 1) { if (t < s) red[t] += red[t + s]; __syncthreads(); }
    row[t] = e / red[0];
}

// ======================= attention-value (one pass over x), emits split v =======================
__global__ void __launch_bounds__(768, 1) attnv_kernel(const float* __restrict__ x) {
    int b = blockIdx.x;
    int tid = threadIdx.x;            // 768
    int ty = tid / 192, tx = tid % 192;
    __shared__ float a[3][Ll];
    __shared__ float4 part[3][4][192];
    const float* att = &g_att[b * NL];
    for (int i = tid; i < NL; i += 768) a[i >> 8][i & 255] = att[i];
    __syncthreads();
    const float4* xb = (const float4*)(x + (size_t)b * Ll * Dd);
    float4 s1 = {0,0,0,0}, s2 = {0,0,0,0}, s3 = {0,0,0,0};
    int l0 = ty * 64;
    #pragma unroll 4
    for (int l = l0; l < l0 + 64; l++) {
        float4 xv = xb[l * (Dd/4) + tx];
        float w1 = a[0][l], w2 = a[1][l], w3 = a[2][l];
        s1.x += w1*xv.x; s1.y += w1*xv.y; s1.z += w1*xv.z; s1.w += w1*xv.w;
        s2.x += w2*xv.x; s2.y += w2*xv.y; s2.z += w2*xv.z; s2.w += w2*xv.w;
        s3.x += w3*xv.x; s3.y += w3*xv.y; s3.z += w3*xv.z; s3.w += w3*xv.w;
    }
    part[0][ty][tx] = s1; part[1][ty][tx] = s2; part[2][ty][tx] = s3;
    __syncthreads();
    if (tid < 576) {
        int h = tid / 192, j = tid % 192;
        float4 p0 = part[h][0][j], p1 = part[h][1][j], p2 = part[h][2][j], p3 = part[h][3][j];
        float r[4] = { p0.x+p1.x+p2.x+p3.x, p0.y+p1.y+p2.y+p3.y,
                       p0.z+p1.z+p2.z+p3.z, p0.w+p1.w+p2.w+p3.w };
        size_t o = (size_t)b * KV + h * Dd + j * 4;
        #pragma unroll
        for (int u = 0; u < 4; u++) split2(r[u], &g_vh_[o + u], &g_vl_[o + u]);
    }
}

// ======================= LSTM pointwise (adds bias), emits split h =======================
__device__ __forceinline__ float sigmoidf_(float x) { return 1.0f / (1.0f + expf(-x)); }

__global__ void lstm_kernel(float* __restrict__ out, int t_step) {
    int idx = blockIdx.x * blockDim.x + threadIdx.x;  // B*H
    int b = idx >> 10, j = idx & 1023;
    const float* gr = &g_gates[(size_t)b * Gg];
    float ig = gr[j]        + g_biasG[j];
    float fg = gr[Hh + j]   + g_biasG[Hh + j];
    float gg = gr[2*Hh + j] + g_biasG[2*Hh + j];
    float og = gr[3*Hh + j] + g_biasG[3*Hh + j];
    float c = g_c[idx];
    float cn = sigmoidf_(fg) * c + sigmoidf_(ig) * tanhf(gg);
    float hn = sigmoidf_(og) * tanhf(cn);
    g_c[idx] = cn;
    split2(hn, &g_hh_[idx], &g_hl_[idx]);
    out[((size_t)b * Tt + t_step) * Hh + j] = hn;
}

// ======================= driver =======================
extern "C" void kernel_launch(void* const* d_in, const int* in_sizes, int n_in,
                              void* d_out, int out_size) {
    (void)in_sizes; (void)n_in; (void)out_size;
    const float* x    = (const float*)d_in[0];
    const float* h0   = (const float*)d_in[1];
    const float* c0   = (const float*)d_in[2];
    const float* W1   = (const float*)d_in[3];
    const float* b1   = (const float*)d_in[4];
    const float* W2   = (const float*)d_in[5];
    const float* b2   = (const float*)d_in[6];
    const float* W3   = (const float*)d_in[7];
    const float* b3   = (const float*)d_in[8];
    const float* W_ih = (const float*)d_in[9];
    const float* W_hh = (const float*)d_in[10];
    const float* b_ih = (const float*)d_in[11];
    const float* b_hh = (const float*)d_in[12];
    float* out = (float*)d_out;

    const int SMEM1 = (2*128 + 2*64) * LDS * 2 * 2;   // 110592
    const int SMEM0 = (2*64  + 2*64) * LDS * 2 * 2;   // 73728
    cudaFuncSetAttribute(gemm_split_kernel<0>, cudaFuncAttributeMaxDynamicSharedMemorySize, SMEM0);
    cudaFuncSetAttribute(gemm_split_kernel<1>, cudaFuncAttributeMaxDynamicSharedMemorySize, SMEM1);

    __nv_bfloat16 *wah, *wal, *wihh, *wihl, *whhh, *whhl;
    cudaGetSymbolAddress((void**)&wah,  g_Wah);
    cudaGetSymbolAddress((void**)&wal,  g_Wal);
    cudaGetSymbolAddress((void**)&wihh, g_Wihh);
    cudaGetSymbolAddress((void**)&wihl, g_Wihl);
    cudaGetSymbolAddress((void**)&whhh, g_Whhh);
    cudaGetSymbolAddress((void**)&whhl, g_Whhl);

    split_kernel<<<4096, 256>>>(W_ih, wihh, wihl, Gg*KV);
    split_kernel<<<4096, 256>>>(W_hh, whhh, whhl, Gg*Hh);
    split_kernel<<<1024, 256>>>(W1, wah,           wal,           Ll*Hh);
    split_kernel<<<1024, 256>>>(W2, wah + Ll*Hh,   wal + Ll*Hh,   Ll*Hh);
    split_kernel<<<1024, 256>>>(W3, wah + 2*Ll*Hh, wal + 2*Ll*Hh, Ll*Hh);
    bias_prep_kernel<<<16, 256>>>(b_ih, b_hh, b1, b2, b3);
    init_kernel<<<(Bb*Hh + 255)/256, 256>>>(h0, c0);

    for (int t = 0; t < Tt; t++) {
        gemm_split_kernel<0><<<dim3(NL/64, Bb/64), 256, SMEM0>>>();
        softmax_kernel<<<dim3(Bb, 3), 256>>>();
        attnv_kernel<<<Bb, 768>>>(x);
        gemm_split_kernel<1><<<dim3(Gg/64, Bb/128), 256, SMEM1>>>();
        lstm_kernel<<<(Bb*Hh + 255)/256, 256>>>(out, t);
    }
}